// round 14
// baseline (speedup 1.0000x reference)
#include <cuda_runtime.h>
#include <cuda_bf16.h>
#include <cstdint>

// Problem constants
#define B_   2
#define N_   4096
#define E_   256
#define H_   8
#define TAU_ 32
#define HD_  32
#define M_   (B_ * N_)
#define SCALING 0.17677669529663687f
#define XSZ  ((size_t)M_ * E_)

// Scratch: projected Q, K, V (fp32)
__device__ float g_proj[3 * XSZ];

// ---------------------------------------------------------------------------
__device__ __forceinline__ uint32_t smem_u32(const void* p) {
    uint32_t a;
    asm("{ .reg .u64 t; cvta.to.shared.u64 t, %1; cvt.u32.u64 %0, t; }"
        : "=r"(a) : "l"(p));
    return a;
}

__device__ __forceinline__ void split_bf16(float x, __nv_bfloat16& h,
                                           __nv_bfloat16& l) {
    h = __float2bfloat16(x);
    l = __float2bfloat16(x - __bfloat162float(h));
}

__device__ __forceinline__ void mma_bf16(float c[4], const uint32_t a[4],
                                         const uint32_t b[2]) {
    asm volatile(
        "mma.sync.aligned.m16n8k16.row.col.f32.bf16.bf16.f32 "
        "{%0,%1,%2,%3}, {%4,%5,%6,%7}, {%8,%9}, {%0,%1,%2,%3};"
        : "+f"(c[0]), "+f"(c[1]), "+f"(c[2]), "+f"(c[3])
        : "r"(a[0]), "r"(a[1]), "r"(a[2]), "r"(a[3]), "r"(b[0]), "r"(b[1]));
}

#define LDSM_X4(R0, R1, R2, R3, ADDR)                                          \
    asm volatile("ldmatrix.sync.aligned.m8n8.x4.shared.b16 {%0,%1,%2,%3}, [%4];" \
                 : "=r"(R0), "=r"(R1), "=r"(R2), "=r"(R3) : "r"(ADDR))

// ---------------------------------------------------------------------------
// Projection GEMM: P = X @ W^T + bias (M=8192, N=256, K=256), z selects X.
// Block 128x64, BK=32, 8 warps (4M x 2N), warp tile 32x32, split-3 bf16.
// Double-buffered software pipeline: LDG chunk c+1 issued before MMA(c),
// converted+stored after; ONE sync per chunk.
// Fragments: ldmatrix.x4; SST=40 -> LDSM rows tile all 32 banks exactly.
// ---------------------------------------------------------------------------
#define SST 40   // bf16 elems per smem row (32 + 8 pad)

__global__ __launch_bounds__(256) void proj_kernel(
        const float* __restrict__ Q,
        const float* __restrict__ K,
        const float* __restrict__ V,
        const float* __restrict__ W,
        const float* __restrict__ bias) {
    __shared__ alignas(16) __nv_bfloat16 sAh[2][128 * SST];
    __shared__ alignas(16) __nv_bfloat16 sAl[2][128 * SST];
    __shared__ alignas(16) __nv_bfloat16 sBh[2][64 * SST];
    __shared__ alignas(16) __nv_bfloat16 sBl[2][64 * SST];

    const float* X = (blockIdx.z == 0) ? Q : (blockIdx.z == 1 ? K : V);
    float* P = g_proj + (size_t)blockIdx.z * XSZ;

    const int tid  = threadIdx.x;
    const int m0   = blockIdx.y << 7;
    const int n0   = blockIdx.x << 6;
    const int lane = tid & 31;
    const int warp = tid >> 5;
    const int g    = lane >> 2;
    const int tig  = lane & 3;
    const int wM   = warp & 3;
    const int wN   = warp >> 2;

    // ldmatrix per-lane element offsets
    const int aoff = (lane & 15) * SST + ((lane >> 4) << 3);
    const int boff = ((lane & 7) + ((lane & 16) >> 1)) * SST
                   + (((lane >> 3) & 1) << 3);

    // Per-thread staging coordinates (fixed across chunks)
    const int arow = tid >> 1;                 // A: rows, 2 thr/row
    const int ac4a = (tid & 1) << 3;           // A: cols 0/8 (+16 second pass)
    const int brow = tid >> 2;                 // B: only tid<256 covers 64 rows *4
    const int bc4  = (tid & 3) << 3;           // B cols 0,8,16,24

    float4 pa[4];   // prefetched A: rows arow (c4 ac4a, ac4a+16... see loads)
    float4 pb[2];

    float acc[2][4][4];
    #pragma unroll
    for (int mi = 0; mi < 2; mi++)
        #pragma unroll
        for (int ni = 0; ni < 4; ni++)
            #pragma unroll
            for (int r = 0; r < 4; r++) acc[mi][ni][r] = 0.f;

    // ---- load helpers (macro-free inline lambdas) ----
    auto load_chunk = [&](int k0) {
        // A 128x32: thread covers rows {tid>>1} cols [ (tid&1)*8, +8 ) in two
        // 4-float pieces, and the same for cols +16. (4 float4 total)
        #pragma unroll
        for (int i = 0; i < 2; i++) {
            int c4 = ac4a + (i << 4);          // 0/8 or 16/24
            pa[2 * i]     = *reinterpret_cast<const float4*>(
                &X[(size_t)(m0 + arow) * E_ + k0 + c4]);
            pa[2 * i + 1] = *reinterpret_cast<const float4*>(
                &X[(size_t)(m0 + arow) * E_ + k0 + c4 + 4]);
        }
        // B 64x32: thread covers row tid>>2, cols (tid&3)*8 .. +8 (2 float4)
        pb[0] = *reinterpret_cast<const float4*>(
            &W[(size_t)(n0 + brow) * E_ + k0 + bc4]);
        pb[1] = *reinterpret_cast<const float4*>(
            &W[(size_t)(n0 + brow) * E_ + k0 + bc4 + 4]);
    };

    auto store_chunk = [&](int bb) {
        __nv_bfloat16 h[4], l[4];
        #pragma unroll
        for (int i = 0; i < 2; i++) {
            int c4 = ac4a + (i << 4);
            #pragma unroll
            for (int half = 0; half < 2; half++) {
                float4 v = pa[2 * i + half];
                split_bf16(v.x, h[0], l[0]);
                split_bf16(v.y, h[1], l[1]);
                split_bf16(v.z, h[2], l[2]);
                split_bf16(v.w, h[3], l[3]);
                int o = arow * SST + c4 + half * 4;
                *reinterpret_cast<ushort4*>(&sAh[bb][o]) =
                    make_ushort4(__bfloat16_as_ushort(h[0]), __bfloat16_as_ushort(h[1]),
                                 __bfloat16_as_ushort(h[2]), __bfloat16_as_ushort(h[3]));
                *reinterpret_cast<ushort4*>(&sAl[bb][o]) =
                    make_ushort4(__bfloat16_as_ushort(l[0]), __bfloat16_as_ushort(l[1]),
                                 __bfloat16_as_ushort(l[2]), __bfloat16_as_ushort(l[3]));
            }
        }
        #pragma unroll
        for (int half = 0; half < 2; half++) {
            float4 v = pb[half];
            split_bf16(v.x, h[0], l[0]);
            split_bf16(v.y, h[1], l[1]);
            split_bf16(v.z, h[2], l[2]);
            split_bf16(v.w, h[3], l[3]);
            int o = brow * SST + bc4 + half * 4;
            *reinterpret_cast<ushort4*>(&sBh[bb][o]) =
                make_ushort4(__bfloat16_as_ushort(h[0]), __bfloat16_as_ushort(h[1]),
                             __bfloat16_as_ushort(h[2]), __bfloat16_as_ushort(h[3]));
            *reinterpret_cast<ushort4*>(&sBl[bb][o]) =
                make_ushort4(__bfloat16_as_ushort(l[0]), __bfloat16_as_ushort(l[1]),
                             __bfloat16_as_ushort(l[2]), __bfloat16_as_ushort(l[3]));
        }
    };

    // Prologue: chunk 0
    load_chunk(0);
    store_chunk(0);
    __syncthreads();

    #pragma unroll 1
    for (int c = 0; c < 8; c++) {
        const int cur = c & 1;
        if (c < 7) load_chunk((c + 1) << 5);   // LDG early, hidden under MMA

        const uint32_t bAh = smem_u32(sAh[cur]), bAl = smem_u32(sAl[cur]);
        const uint32_t bBh = smem_u32(sBh[cur]), bBl = smem_u32(sBl[cur]);
        #pragma unroll
        for (int kk = 0; kk < 32; kk += 16) {
            uint32_t ah[2][4], al[2][4], bh[4][2], bl[4][2];
            #pragma unroll
            for (int mi = 0; mi < 2; mi++) {
                uint32_t ea = 2u * (uint32_t)((wM * 32 + mi * 16) * SST + aoff + kk);
                LDSM_X4(ah[mi][0], ah[mi][1], ah[mi][2], ah[mi][3], bAh + ea);
                LDSM_X4(al[mi][0], al[mi][1], al[mi][2], al[mi][3], bAl + ea);
            }
            #pragma unroll
            for (int p = 0; p < 2; p++) {
                uint32_t eb = 2u * (uint32_t)((wN * 32 + p * 16) * SST + boff + kk);
                LDSM_X4(bh[2*p][0], bh[2*p][1], bh[2*p+1][0], bh[2*p+1][1], bBh + eb);
                LDSM_X4(bl[2*p][0], bl[2*p][1], bl[2*p+1][0], bl[2*p+1][1], bBl + eb);
            }
            #pragma unroll
            for (int mi = 0; mi < 2; mi++)
                #pragma unroll
                for (int ni = 0; ni < 4; ni++) {
                    mma_bf16(acc[mi][ni], ah[mi], bh[ni]);
                    mma_bf16(acc[mi][ni], ah[mi], bl[ni]);
                    mma_bf16(acc[mi][ni], al[mi], bh[ni]);
                }
        }

        if (c < 7) {
            store_chunk(cur ^ 1);
            __syncthreads();
        }
    }

    // Epilogue (layout validated in round 6)
    #pragma unroll
    for (int mi = 0; mi < 2; mi++) {
        int row = m0 + wM * 32 + mi * 16 + g;
        #pragma unroll
        for (int ni = 0; ni < 4; ni++) {
            int col = n0 + wN * 32 + ni * 8 + tig * 2;
            float2 bb = *reinterpret_cast<const float2*>(&bias[col]);
            float2 o0 = {acc[mi][ni][0] + bb.x, acc[mi][ni][1] + bb.y};
            float2 o1 = {acc[mi][ni][2] + bb.x, acc[mi][ni][3] + bb.y};
            *reinterpret_cast<float2*>(&P[(size_t)row       * E_ + col]) = o0;
            *reinterpret_cast<float2*>(&P[(size_t)(row + 8) * E_ + col]) = o1;
        }
    }
}

// ---------------------------------------------------------------------------
// Sliding-window attention (round-10 validated, verbatim).
// ---------------------------------------------------------------------------
__global__ __launch_bounds__(256) void attn_kernel(
        const float* __restrict__ bias,
        float* __restrict__ out) {
    const int QT = 64, ROWS = QT + TAU_ - 1, S = 36;

    __shared__ float sK[ROWS][S];
    __shared__ float sV[ROWS][S];
    __shared__ float sP[QT][33];

    const int tid  = threadIdx.x;
    const int tile = blockIdx.x & 63;
    const int h    = (blockIdx.x >> 6) & 7;
    const int b    = blockIdx.x >> 9;
    const int n0   = tile * QT;
    const int be   = h * HD_;

    const float* Qp = g_proj;
    const float* Kp = g_proj + XSZ;
    const float* Vp = g_proj + 2 * XSZ;

    for (int i = tid; i < ROWS * 8; i += 256) {
        int row = i >> 3, c = i & 7;
        int r = n0 - (TAU_ - 1) + row;
        float4 kv, vv;
        if (r >= 0) {
            size_t off = ((size_t)(b * N_ + r)) * E_ + be;
            kv = reinterpret_cast<const float4*>(&Kp[off])[c];
            vv = reinterpret_cast<const float4*>(&Vp[off])[c];
        } else {
            kv = reinterpret_cast<const float4*>(&bias[be])[c];
            vv = kv;
        }
        *reinterpret_cast<float4*>(&sK[row][c << 2]) = kv;
        *reinterpret_cast<float4*>(&sV[row][c << 2]) = vv;
    }
    __syncthreads();

    const int p   = tid >> 3;
    const int sub = tid & 7;
    const int lq0 = p << 1;
    const int t0  = sub << 2;

    float d0[5] = {0.f, 0.f, 0.f, 0.f, 0.f};
    float d1[5] = {0.f, 0.f, 0.f, 0.f, 0.f};
    const float* q0p = &Qp[((size_t)(b * N_ + n0 + lq0)) * E_ + be];
    #pragma unroll
    for (int c = 0; c < 4; c++) {
        float4 qa0 = *reinterpret_cast<const float4*>(q0p + (c << 3));
        float4 qa1 = *reinterpret_cast<const float4*>(q0p + (c << 3) + 4);
        float4 qb0 = *reinterpret_cast<const float4*>(q0p + E_ + (c << 3));
        float4 qb1 = *reinterpret_cast<const float4*>(q0p + E_ + (c << 3) + 4);
        #pragma unroll
        for (int j = 0; j < 5; j++) {
            const float* kr = &sK[lq0 + t0 + j][c << 3];
            float4 k0v = *reinterpret_cast<const float4*>(kr);
            float4 k1v = *reinterpret_cast<const float4*>(kr + 4);
            d0[j] += qa0.x * k0v.x + qa0.y * k0v.y + qa0.z * k0v.z + qa0.w * k0v.w
                   + qa1.x * k1v.x + qa1.y * k1v.y + qa1.z * k1v.z + qa1.w * k1v.w;
            d1[j] += qb0.x * k0v.x + qb0.y * k0v.y + qb0.z * k0v.z + qb0.w * k0v.w
                   + qb1.x * k1v.x + qb1.y * k1v.y + qb1.z * k1v.z + qb1.w * k1v.w;
        }
    }
    float s0[4], s1[4];
    #pragma unroll
    for (int j = 0; j < 4; j++) {
        s0[j] = d0[j] * SCALING;
        s1[j] = d1[j + 1] * SCALING;
    }

    float mx0 = fmaxf(fmaxf(s0[0], s0[1]), fmaxf(s0[2], s0[3]));
    float mx1 = fmaxf(fmaxf(s1[0], s1[1]), fmaxf(s1[2], s1[3]));
    #pragma unroll
    for (int m = 1; m <= 4; m <<= 1) {
        mx0 = fmaxf(mx0, __shfl_xor_sync(0xffffffffu, mx0, m));
        mx1 = fmaxf(mx1, __shfl_xor_sync(0xffffffffu, mx1, m));
    }
    float sum0 = 0.f, sum1 = 0.f;
    #pragma unroll
    for (int j = 0; j < 4; j++) {
        s0[j] = __expf(s0[j] - mx0); sum0 += s0[j];
        s1[j] = __expf(s1[j] - mx1); sum1 += s1[j];
    }
    #pragma unroll
    for (int m = 1; m <= 4; m <<= 1) {
        sum0 += __shfl_xor_sync(0xffffffffu, sum0, m);
        sum1 += __shfl_xor_sync(0xffffffffu, sum1, m);
    }
    float inv0 = 1.f / sum0, inv1 = 1.f / sum1;
    #pragma unroll
    for (int j = 0; j < 4; j++) {
        sP[lq0][t0 + j]     = s0[j] * inv0;
        sP[lq0 + 1][t0 + j] = s1[j] * inv1;
    }
    __syncthreads();

    const int d0c = sub << 2;
    float4 o0 = {0.f, 0.f, 0.f, 0.f};
    float4 o1 = {0.f, 0.f, 0.f, 0.f};
    {
        float pr = sP[lq0][0];
        float4 v = *reinterpret_cast<const float4*>(&sV[lq0][d0c]);
        o0.x += pr * v.x; o0.y += pr * v.y; o0.z += pr * v.z; o0.w += pr * v.w;
    }
    #pragma unroll
    for (int r = 1; r < 32; r++) {
        float4 v = *reinterpret_cast<const float4*>(&sV[lq0 + r][d0c]);
        float p0r = sP[lq0][r];
        float p1r = sP[lq0 + 1][r - 1];
        o0.x += p0r * v.x; o0.y += p0r * v.y; o0.z += p0r * v.z; o0.w += p0r * v.w;
        o1.x += p1r * v.x; o1.y += p1r * v.y; o1.z += p1r * v.z; o1.w += p1r * v.w;
    }
    {
        float pr = sP[lq0 + 1][31];
        float4 v = *reinterpret_cast<const float4*>(&sV[lq0 + 32][d0c]);
        o1.x += pr * v.x; o1.y += pr * v.y; o1.z += pr * v.z; o1.w += pr * v.w;
    }

    float* orow = &out[((size_t)(b * N_ + n0 + lq0)) * E_ + be + d0c];
    *reinterpret_cast<float4*>(orow)      = o0;
    *reinterpret_cast<float4*>(orow + E_) = o1;
}

// ---------------------------------------------------------------------------
// Launch
// ---------------------------------------------------------------------------
extern "C" void kernel_launch(void* const* d_in, const int* in_sizes, int n_in,
                              void* d_out, int out_size) {
    const float* query = (const float*)d_in[0];
    const float* key   = (const float*)d_in[1];
    const float* value = (const float*)d_in[2];
    const float* W     = (const float*)d_in[3];
    const float* bias  = (const float*)d_in[4];
    float* out = (float*)d_out;

    dim3 gProj(E_ / 64, M_ / 128, 3);   // (4, 64, 3)
    proj_kernel<<<gProj, 256>>>(query, key, value, W, bias);

    attn_kernel<<<B_ * H_ * (N_ / 64), 256>>>(bias, out);
}

// round 15
// speedup vs baseline: 1.1421x; 1.1421x over previous
#include <cuda_runtime.h>
#include <cuda_bf16.h>
#include <cstdint>

// Problem constants
#define B_   2
#define N_   4096
#define E_   256
#define H_   8
#define TAU_ 32
#define HD_  32
#define M_   (B_ * N_)
#define SCALING 0.17677669529663687f
#define XSZ  ((size_t)M_ * E_)

// Scratch: projected Q, K, V (fp32)
__device__ float g_proj[3 * XSZ];

// ---------------------------------------------------------------------------
__device__ __forceinline__ uint32_t smem_u32(const void* p) {
    uint32_t a;
    asm("{ .reg .u64 t; cvta.to.shared.u64 t, %1; cvt.u32.u64 %0, t; }"
        : "=r"(a) : "l"(p));
    return a;
}

__device__ __forceinline__ void split_bf16(float x, __nv_bfloat16& h,
                                           __nv_bfloat16& l) {
    h = __float2bfloat16(x);
    l = __float2bfloat16(x - __bfloat162float(h));
}

__device__ __forceinline__ void mma_bf16(float c[4], const uint32_t a[4],
                                         const uint32_t b[2]) {
    asm volatile(
        "mma.sync.aligned.m16n8k16.row.col.f32.bf16.bf16.f32 "
        "{%0,%1,%2,%3}, {%4,%5,%6,%7}, {%8,%9}, {%0,%1,%2,%3};"
        : "+f"(c[0]), "+f"(c[1]), "+f"(c[2]), "+f"(c[3])
        : "r"(a[0]), "r"(a[1]), "r"(a[2]), "r"(a[3]), "r"(b[0]), "r"(b[1]));
}

#define LDSM_X4(R0, R1, R2, R3, ADDR)                                          \
    asm volatile("ldmatrix.sync.aligned.m8n8.x4.shared.b16 {%0,%1,%2,%3}, [%4];" \
                 : "=r"(R0), "=r"(R1), "=r"(R2), "=r"(R3) : "r"(ADDR))

// ---------------------------------------------------------------------------
// Projection GEMM (round-13 validated, 35.4us): P = X @ W^T + bias.
// Block 128x64, BK=32, 8 warps (4M x 2N), warp tile 32x32, split-3 bf16.
// Staging: inline split (ushort4). Fragments: ldmatrix.x4, SST=40.
// ---------------------------------------------------------------------------
#define SST 40

__global__ __launch_bounds__(256) void proj_kernel(
        const float* __restrict__ Q,
        const float* __restrict__ K,
        const float* __restrict__ V,
        const float* __restrict__ W,
        const float* __restrict__ bias) {
    __shared__ alignas(16) __nv_bfloat16 sAh[128 * SST];
    __shared__ alignas(16) __nv_bfloat16 sAl[128 * SST];
    __shared__ alignas(16) __nv_bfloat16 sBh[64 * SST];
    __shared__ alignas(16) __nv_bfloat16 sBl[64 * SST];

    const float* X = (blockIdx.z == 0) ? Q : (blockIdx.z == 1 ? K : V);
    float* P = g_proj + (size_t)blockIdx.z * XSZ;

    const int tid  = threadIdx.x;
    const int m0   = blockIdx.y << 7;
    const int n0   = blockIdx.x << 6;
    const int lane = tid & 31;
    const int warp = tid >> 5;
    const int g    = lane >> 2;
    const int tig  = lane & 3;
    const int wM   = warp & 3;
    const int wN   = warp >> 2;

    const uint32_t bAh = smem_u32(sAh), bAl = smem_u32(sAl);
    const uint32_t bBh = smem_u32(sBh), bBl = smem_u32(sBl);
    const int aoff = (lane & 15) * SST + ((lane >> 4) << 3);
    const int boff = ((lane & 7) + ((lane & 16) >> 1)) * SST
                   + (((lane >> 3) & 1) << 3);

    float acc[2][4][4];
    #pragma unroll
    for (int mi = 0; mi < 2; mi++)
        #pragma unroll
        for (int ni = 0; ni < 4; ni++)
            #pragma unroll
            for (int r = 0; r < 4; r++) acc[mi][ni][r] = 0.f;

    #pragma unroll 1
    for (int k0 = 0; k0 < E_; k0 += 32) {
        __syncthreads();
        #pragma unroll
        for (int i = 0; i < 4; i++) {
            int e   = tid + (i << 8);
            int row = e >> 3;
            int c4  = (e & 7) << 2;
            float4 v = *reinterpret_cast<const float4*>(
                &X[(size_t)(m0 + row) * E_ + k0 + c4]);
            __nv_bfloat16 h[4], l[4];
            split_bf16(v.x, h[0], l[0]);
            split_bf16(v.y, h[1], l[1]);
            split_bf16(v.z, h[2], l[2]);
            split_bf16(v.w, h[3], l[3]);
            int o = row * SST + c4;
            *reinterpret_cast<ushort4*>(&sAh[o]) =
                make_ushort4(__bfloat16_as_ushort(h[0]), __bfloat16_as_ushort(h[1]),
                             __bfloat16_as_ushort(h[2]), __bfloat16_as_ushort(h[3]));
            *reinterpret_cast<ushort4*>(&sAl[o]) =
                make_ushort4(__bfloat16_as_ushort(l[0]), __bfloat16_as_ushort(l[1]),
                             __bfloat16_as_ushort(l[2]), __bfloat16_as_ushort(l[3]));
        }
        #pragma unroll
        for (int i = 0; i < 2; i++) {
            int e   = tid + (i << 8);
            int row = e >> 3;
            int c4  = (e & 7) << 2;
            float4 v = *reinterpret_cast<const float4*>(
                &W[(size_t)(n0 + row) * E_ + k0 + c4]);
            __nv_bfloat16 h[4], l[4];
            split_bf16(v.x, h[0], l[0]);
            split_bf16(v.y, h[1], l[1]);
            split_bf16(v.z, h[2], l[2]);
            split_bf16(v.w, h[3], l[3]);
            int o = row * SST + c4;
            *reinterpret_cast<ushort4*>(&sBh[o]) =
                make_ushort4(__bfloat16_as_ushort(h[0]), __bfloat16_as_ushort(h[1]),
                             __bfloat16_as_ushort(h[2]), __bfloat16_as_ushort(h[3]));
            *reinterpret_cast<ushort4*>(&sBl[o]) =
                make_ushort4(__bfloat16_as_ushort(l[0]), __bfloat16_as_ushort(l[1]),
                             __bfloat16_as_ushort(l[2]), __bfloat16_as_ushort(l[3]));
        }
        __syncthreads();

        #pragma unroll
        for (int kk = 0; kk < 32; kk += 16) {
            uint32_t ah[2][4], al[2][4], bh[4][2], bl[4][2];
            #pragma unroll
            for (int mi = 0; mi < 2; mi++) {
                uint32_t ea = 2u * (uint32_t)((wM * 32 + mi * 16) * SST + aoff + kk);
                LDSM_X4(ah[mi][0], ah[mi][1], ah[mi][2], ah[mi][3], bAh + ea);
                LDSM_X4(al[mi][0], al[mi][1], al[mi][2], al[mi][3], bAl + ea);
            }
            #pragma unroll
            for (int p = 0; p < 2; p++) {
                uint32_t eb = 2u * (uint32_t)((wN * 32 + p * 16) * SST + boff + kk);
                LDSM_X4(bh[2*p][0], bh[2*p][1], bh[2*p+1][0], bh[2*p+1][1], bBh + eb);
                LDSM_X4(bl[2*p][0], bl[2*p][1], bl[2*p+1][0], bl[2*p+1][1], bBl + eb);
            }
            #pragma unroll
            for (int mi = 0; mi < 2; mi++)
                #pragma unroll
                for (int ni = 0; ni < 4; ni++) {
                    mma_bf16(acc[mi][ni], ah[mi], bh[ni]);
                    mma_bf16(acc[mi][ni], ah[mi], bl[ni]);
                    mma_bf16(acc[mi][ni], al[mi], bh[ni]);
                }
        }
    }

    #pragma unroll
    for (int mi = 0; mi < 2; mi++) {
        int row = m0 + wM * 32 + mi * 16 + g;
        #pragma unroll
        for (int ni = 0; ni < 4; ni++) {
            int col = n0 + wN * 32 + ni * 8 + tig * 2;
            float2 bb = *reinterpret_cast<const float2*>(&bias[col]);
            float2 o0 = {acc[mi][ni][0] + bb.x, acc[mi][ni][1] + bb.y};
            float2 o1 = {acc[mi][ni][2] + bb.x, acc[mi][ni][3] + bb.y};
            *reinterpret_cast<float2*>(&P[(size_t)row       * E_ + col]) = o0;
            *reinterpret_cast<float2*>(&P[(size_t)(row + 8) * E_ + col]) = o1;
        }
    }
}

// ---------------------------------------------------------------------------
// Sliding-window attention, 4-query grouping.
// Block = (b, h, 64-query tile), 128 threads = 16 quads x 8 threads.
// Thread (quad, s): scores for queries q0..q0+3, t = 4s..4s+3 -> 7 K rows
// serve 16 scores. Output: queries q0..q0+3, dims 4s..4s+3 -> 35 V rows
// serve 4 outputs. Probabilities in zero-padded sP (col 3+t) for
// branch-free output accumulation.
// ---------------------------------------------------------------------------
__global__ __launch_bounds__(128) void attn_kernel(
        const float* __restrict__ bias,
        float* __restrict__ out) {
    const int QT = 64, ROWS = QT + TAU_ - 1, S = 36, PW = 38;

    __shared__ float sK[ROWS][S];
    __shared__ float sV[ROWS][S];
    __shared__ float sP[QT][PW];     // prob at [q][3 + t]; borders zero

    const int tid  = threadIdx.x;
    const int tile = blockIdx.x & 63;
    const int h    = (blockIdx.x >> 6) & 7;
    const int b    = blockIdx.x >> 9;
    const int n0   = tile * QT;
    const int be   = h * HD_;

    const float* Qp = g_proj;
    const float* Kp = g_proj + XSZ;
    const float* Vp = g_proj + 2 * XSZ;

    // Zero-init sP borders (init whole array; cheap)
    for (int i = tid; i < QT * PW / 2; i += 128) {
        int q = i / (PW / 2), c = i % (PW / 2);
        *reinterpret_cast<float2*>(&sP[q][c * 2]) = make_float2(0.f, 0.f);
    }

    // Stage K/V window rows [n0-31, n0+63]; pre-sequence rows = bias vector.
    for (int i = tid; i < ROWS * 8; i += 128) {
        int row = i >> 3, c = i & 7;
        int r = n0 - (TAU_ - 1) + row;
        float4 kv, vv;
        if (r >= 0) {
            size_t off = ((size_t)(b * N_ + r)) * E_ + be;
            kv = reinterpret_cast<const float4*>(&Kp[off])[c];
            vv = reinterpret_cast<const float4*>(&Vp[off])[c];
        } else {
            kv = reinterpret_cast<const float4*>(&bias[be])[c];
            vv = kv;
        }
        *reinterpret_cast<float4*>(&sK[row][c << 2]) = kv;
        *reinterpret_cast<float4*>(&sV[row][c << 2]) = vv;
    }
    __syncthreads();

    const int quad = tid >> 3;       // 0..15
    const int s    = tid & 7;        // 0..7
    const int q0   = quad << 2;      // local query base
    const int t0   = s << 2;         // t base

    // Scores: acc[qi][ti], K row j = q0 + t0 + j serves pairs qi+ti=j.
    float acc[4][4];
    #pragma unroll
    for (int qi = 0; qi < 4; qi++)
        #pragma unroll
        for (int ti = 0; ti < 4; ti++) acc[qi][ti] = 0.f;

    const float* qbase = &Qp[((size_t)(b * N_ + n0 + q0)) * E_ + be];
    #pragma unroll
    for (int c = 0; c < 4; c++) {
        float4 qv[4][2];
        #pragma unroll
        for (int qi = 0; qi < 4; qi++) {
            qv[qi][0] = *reinterpret_cast<const float4*>(qbase + qi * E_ + (c << 3));
            qv[qi][1] = *reinterpret_cast<const float4*>(qbase + qi * E_ + (c << 3) + 4);
        }
        #pragma unroll
        for (int j = 0; j < 7; j++) {
            const float* kr = &sK[q0 + t0 + j][c << 3];
            float4 k0 = *reinterpret_cast<const float4*>(kr);
            float4 k1 = *reinterpret_cast<const float4*>(kr + 4);
            #pragma unroll
            for (int qi = 0; qi < 4; qi++) {
                int ti = j - qi;
                if (ti >= 0 && ti < 4) {
                    acc[qi][ti] += qv[qi][0].x * k0.x + qv[qi][0].y * k0.y
                                 + qv[qi][0].z * k0.z + qv[qi][0].w * k0.w
                                 + qv[qi][1].x * k1.x + qv[qi][1].y * k1.y
                                 + qv[qi][1].z * k1.z + qv[qi][1].w * k1.w;
                }
            }
        }
    }

    // Softmax per query across the 8 lanes of the quad-group (xor 1,2,4)
    #pragma unroll
    for (int qi = 0; qi < 4; qi++) {
        float sc[4];
        #pragma unroll
        for (int ti = 0; ti < 4; ti++) sc[ti] = acc[qi][ti] * SCALING;
        float mx = fmaxf(fmaxf(sc[0], sc[1]), fmaxf(sc[2], sc[3]));
        #pragma unroll
        for (int m = 1; m <= 4; m <<= 1)
            mx = fmaxf(mx, __shfl_xor_sync(0xffffffffu, mx, m));
        float sum = 0.f;
        #pragma unroll
        for (int ti = 0; ti < 4; ti++) {
            sc[ti] = __expf(sc[ti] - mx);
            sum += sc[ti];
        }
        #pragma unroll
        for (int m = 1; m <= 4; m <<= 1)
            sum += __shfl_xor_sync(0xffffffffu, sum, m);
        float inv = 1.f / sum;
        #pragma unroll
        for (int ti = 0; ti < 4; ti++)
            sP[q0 + qi][3 + t0 + ti] = sc[ti] * inv;
    }
    __syncthreads();

    // Output: V row q0+rr (rr=0..34) feeds query qi at t = rr - qi.
    const int d0 = s << 2;
    float4 o[4];
    #pragma unroll
    for (int qi = 0; qi < 4; qi++) o[qi] = make_float4(0.f, 0.f, 0.f, 0.f);

    #pragma unroll
    for (int rr = 0; rr < 35; rr++) {
        float4 v = *reinterpret_cast<const float4*>(&sV[q0 + rr][d0]);
        #pragma unroll
        for (int qi = 0; qi < 4; qi++) {
            float p = sP[q0 + qi][3 + rr - qi];   // zero outside valid band
            o[qi].x += p * v.x; o[qi].y += p * v.y;
            o[qi].z += p * v.z; o[qi].w += p * v.w;
        }
    }

    #pragma unroll
    for (int qi = 0; qi < 4; qi++) {
        float* orow = &out[((size_t)(b * N_ + n0 + q0 + qi)) * E_ + be + d0];
        *reinterpret_cast<float4*>(orow) = o[qi];
    }
}

// ---------------------------------------------------------------------------
// Launch
// ---------------------------------------------------------------------------
extern "C" void kernel_launch(void* const* d_in, const int* in_sizes, int n_in,
                              void* d_out, int out_size) {
    const float* query = (const float*)d_in[0];
    const float* key   = (const float*)d_in[1];
    const float* value = (const float*)d_in[2];
    const float* W     = (const float*)d_in[3];
    const float* bias  = (const float*)d_in[4];
    float* out = (float*)d_out;

    dim3 gProj(E_ / 64, M_ / 128, 3);   // (4, 64, 3)
    proj_kernel<<<gProj, 256>>>(query, key, value, W, bias);

    attn_kernel<<<B_ * H_ * (N_ / 64), 128>>>(bias, out);
}

// round 16
// speedup vs baseline: 1.1593x; 1.0150x over previous
#include <cuda_runtime.h>
#include <cuda_bf16.h>
#include <cstdint>

// Problem constants
#define B_   2
#define N_   4096
#define E_   256
#define H_   8
#define TAU_ 32
#define HD_  32
#define M_   (B_ * N_)
#define SCALING 0.17677669529663687f
#define XSZ  ((size_t)M_ * E_)

// Scratch: projected Q, K, V (fp32)
__device__ float g_proj[3 * XSZ];

// ---------------------------------------------------------------------------
__device__ __forceinline__ uint32_t smem_u32(const void* p) {
    uint32_t a;
    asm("{ .reg .u64 t; cvta.to.shared.u64 t, %1; cvt.u32.u64 %0, t; }"
        : "=r"(a) : "l"(p));
    return a;
}

__device__ __forceinline__ void split_bf16(float x, __nv_bfloat16& h,
                                           __nv_bfloat16& l) {
    h = __float2bfloat16(x);
    l = __float2bfloat16(x - __bfloat162float(h));
}

__device__ __forceinline__ void mma_bf16(float c[4], const uint32_t a[4],
                                         const uint32_t b[2]) {
    asm volatile(
        "mma.sync.aligned.m16n8k16.row.col.f32.bf16.bf16.f32 "
        "{%0,%1,%2,%3}, {%4,%5,%6,%7}, {%8,%9}, {%0,%1,%2,%3};"
        : "+f"(c[0]), "+f"(c[1]), "+f"(c[2]), "+f"(c[3])
        : "r"(a[0]), "r"(a[1]), "r"(a[2]), "r"(a[3]), "r"(b[0]), "r"(b[1]));
}

#define LDSM_X4(R0, R1, R2, R3, ADDR)                                          \
    asm volatile("ldmatrix.sync.aligned.m8n8.x4.shared.b16 {%0,%1,%2,%3}, [%4];" \
                 : "=r"(R0), "=r"(R1), "=r"(R2), "=r"(R3) : "r"(ADDR))

// ---------------------------------------------------------------------------
// Projection GEMM (round-13 validated, 35.4us): P = X @ W^T + bias.
// Block 128x64, BK=32, 8 warps (4M x 2N), warp tile 32x32, split-3 bf16.
// Staging: inline split (ushort4). Fragments: ldmatrix.x4, SST=40.
// ---------------------------------------------------------------------------
#define SST 40

__global__ __launch_bounds__(256) void proj_kernel(
        const float* __restrict__ Q,
        const float* __restrict__ K,
        const float* __restrict__ V,
        const float* __restrict__ W,
        const float* __restrict__ bias) {
    __shared__ alignas(16) __nv_bfloat16 sAh[128 * SST];
    __shared__ alignas(16) __nv_bfloat16 sAl[128 * SST];
    __shared__ alignas(16) __nv_bfloat16 sBh[64 * SST];
    __shared__ alignas(16) __nv_bfloat16 sBl[64 * SST];

    const float* X = (blockIdx.z == 0) ? Q : (blockIdx.z == 1 ? K : V);
    float* P = g_proj + (size_t)blockIdx.z * XSZ;

    const int tid  = threadIdx.x;
    const int m0   = blockIdx.y << 7;
    const int n0   = blockIdx.x << 6;
    const int lane = tid & 31;
    const int warp = tid >> 5;
    const int g    = lane >> 2;
    const int tig  = lane & 3;
    const int wM   = warp & 3;
    const int wN   = warp >> 2;

    const uint32_t bAh = smem_u32(sAh), bAl = smem_u32(sAl);
    const uint32_t bBh = smem_u32(sBh), bBl = smem_u32(sBl);
    const int aoff = (lane & 15) * SST + ((lane >> 4) << 3);
    const int boff = ((lane & 7) + ((lane & 16) >> 1)) * SST
                   + (((lane >> 3) & 1) << 3);

    float acc[2][4][4];
    #pragma unroll
    for (int mi = 0; mi < 2; mi++)
        #pragma unroll
        for (int ni = 0; ni < 4; ni++)
            #pragma unroll
            for (int r = 0; r < 4; r++) acc[mi][ni][r] = 0.f;

    #pragma unroll 1
    for (int k0 = 0; k0 < E_; k0 += 32) {
        __syncthreads();
        #pragma unroll
        for (int i = 0; i < 4; i++) {
            int e   = tid + (i << 8);
            int row = e >> 3;
            int c4  = (e & 7) << 2;
            float4 v = *reinterpret_cast<const float4*>(
                &X[(size_t)(m0 + row) * E_ + k0 + c4]);
            __nv_bfloat16 h[4], l[4];
            split_bf16(v.x, h[0], l[0]);
            split_bf16(v.y, h[1], l[1]);
            split_bf16(v.z, h[2], l[2]);
            split_bf16(v.w, h[3], l[3]);
            int o = row * SST + c4;
            *reinterpret_cast<ushort4*>(&sAh[o]) =
                make_ushort4(__bfloat16_as_ushort(h[0]), __bfloat16_as_ushort(h[1]),
                             __bfloat16_as_ushort(h[2]), __bfloat16_as_ushort(h[3]));
            *reinterpret_cast<ushort4*>(&sAl[o]) =
                make_ushort4(__bfloat16_as_ushort(l[0]), __bfloat16_as_ushort(l[1]),
                             __bfloat16_as_ushort(l[2]), __bfloat16_as_ushort(l[3]));
        }
        #pragma unroll
        for (int i = 0; i < 2; i++) {
            int e   = tid + (i << 8);
            int row = e >> 3;
            int c4  = (e & 7) << 2;
            float4 v = *reinterpret_cast<const float4*>(
                &W[(size_t)(n0 + row) * E_ + k0 + c4]);
            __nv_bfloat16 h[4], l[4];
            split_bf16(v.x, h[0], l[0]);
            split_bf16(v.y, h[1], l[1]);
            split_bf16(v.z, h[2], l[2]);
            split_bf16(v.w, h[3], l[3]);
            int o = row * SST + c4;
            *reinterpret_cast<ushort4*>(&sBh[o]) =
                make_ushort4(__bfloat16_as_ushort(h[0]), __bfloat16_as_ushort(h[1]),
                             __bfloat16_as_ushort(h[2]), __bfloat16_as_ushort(h[3]));
            *reinterpret_cast<ushort4*>(&sBl[o]) =
                make_ushort4(__bfloat16_as_ushort(l[0]), __bfloat16_as_ushort(l[1]),
                             __bfloat16_as_ushort(l[2]), __bfloat16_as_ushort(l[3]));
        }
        __syncthreads();

        #pragma unroll
        for (int kk = 0; kk < 32; kk += 16) {
            uint32_t ah[2][4], al[2][4], bh[4][2], bl[4][2];
            #pragma unroll
            for (int mi = 0; mi < 2; mi++) {
                uint32_t ea = 2u * (uint32_t)((wM * 32 + mi * 16) * SST + aoff + kk);
                LDSM_X4(ah[mi][0], ah[mi][1], ah[mi][2], ah[mi][3], bAh + ea);
                LDSM_X4(al[mi][0], al[mi][1], al[mi][2], al[mi][3], bAl + ea);
            }
            #pragma unroll
            for (int p = 0; p < 2; p++) {
                uint32_t eb = 2u * (uint32_t)((wN * 32 + p * 16) * SST + boff + kk);
                LDSM_X4(bh[2*p][0], bh[2*p][1], bh[2*p+1][0], bh[2*p+1][1], bBh + eb);
                LDSM_X4(bl[2*p][0], bl[2*p][1], bl[2*p+1][0], bl[2*p+1][1], bBl + eb);
            }
            #pragma unroll
            for (int mi = 0; mi < 2; mi++)
                #pragma unroll
                for (int ni = 0; ni < 4; ni++) {
                    mma_bf16(acc[mi][ni], ah[mi], bh[ni]);
                    mma_bf16(acc[mi][ni], ah[mi], bl[ni]);
                    mma_bf16(acc[mi][ni], al[mi], bh[ni]);
                }
        }
    }

    #pragma unroll
    for (int mi = 0; mi < 2; mi++) {
        int row = m0 + wM * 32 + mi * 16 + g;
        #pragma unroll
        for (int ni = 0; ni < 4; ni++) {
            int col = n0 + wN * 32 + ni * 8 + tig * 2;
            float2 bb = *reinterpret_cast<const float2*>(&bias[col]);
            float2 o0 = {acc[mi][ni][0] + bb.x, acc[mi][ni][1] + bb.y};
            float2 o1 = {acc[mi][ni][2] + bb.x, acc[mi][ni][3] + bb.y};
            *reinterpret_cast<float2*>(&P[(size_t)row       * E_ + col]) = o0;
            *reinterpret_cast<float2*>(&P[(size_t)(row + 8) * E_ + col]) = o1;
        }
    }
}

// ---------------------------------------------------------------------------
// Sliding-window attention, hybrid mapping.
// Block = (b, h, 64-query tile), 256 threads.
// Score phase: round-10 validated 2-query pairing (32 pairs x 8 threads).
// Output phase: remapped to 16 quads x 16 threads; each thread does
// 4 queries x 2 dims -> 35 V-row float2 loads serve 8 outputs (-47% V
// traffic). Branch-free via zero-padded sP (prob at col 3+t).
// ---------------------------------------------------------------------------
__global__ __launch_bounds__(256) void attn_kernel(
        const float* __restrict__ bias,
        float* __restrict__ out) {
    const int QT = 64, ROWS = QT + TAU_ - 1, S = 36, PW = 38;

    __shared__ float sK[ROWS][S];
    __shared__ float sV[ROWS][S];
    __shared__ float sP[QT][PW];     // prob at [q][3 + t]; borders zero

    const int tid  = threadIdx.x;
    const int tile = blockIdx.x & 63;
    const int h    = (blockIdx.x >> 6) & 7;
    const int b    = blockIdx.x >> 9;
    const int n0   = tile * QT;
    const int be   = h * HD_;

    const float* Qp = g_proj;
    const float* Kp = g_proj + XSZ;
    const float* Vp = g_proj + 2 * XSZ;

    // Zero sP (covers pad borders); barrier below separates from score writes
    for (int i = tid; i < QT * PW / 2; i += 256)
        *reinterpret_cast<float2*>(&sP[0][0] + 2 * i) = make_float2(0.f, 0.f);

    // Stage K/V window rows [n0-31, n0+63]; pre-sequence rows = bias vector.
    for (int i = tid; i < ROWS * 8; i += 256) {
        int row = i >> 3, c = i & 7;
        int r = n0 - (TAU_ - 1) + row;
        float4 kv, vv;
        if (r >= 0) {
            size_t off = ((size_t)(b * N_ + r)) * E_ + be;
            kv = reinterpret_cast<const float4*>(&Kp[off])[c];
            vv = reinterpret_cast<const float4*>(&Vp[off])[c];
        } else {
            kv = reinterpret_cast<const float4*>(&bias[be])[c];
            vv = kv;
        }
        *reinterpret_cast<float4*>(&sK[row][c << 2]) = kv;
        *reinterpret_cast<float4*>(&sV[row][c << 2]) = vv;
    }
    __syncthreads();

    // ---- Score phase (round-10 mapping): pair p, t-slice sub ----
    const int p   = tid >> 3;        // pair 0..31
    const int sub = tid & 7;         // 0..7
    const int lq0 = p << 1;
    const int t0  = sub << 2;

    float d0[5] = {0.f, 0.f, 0.f, 0.f, 0.f};
    float d1[5] = {0.f, 0.f, 0.f, 0.f, 0.f};
    const float* q0p = &Qp[((size_t)(b * N_ + n0 + lq0)) * E_ + be];
    #pragma unroll
    for (int c = 0; c < 4; c++) {
        float4 qa0 = *reinterpret_cast<const float4*>(q0p + (c << 3));
        float4 qa1 = *reinterpret_cast<const float4*>(q0p + (c << 3) + 4);
        float4 qb0 = *reinterpret_cast<const float4*>(q0p + E_ + (c << 3));
        float4 qb1 = *reinterpret_cast<const float4*>(q0p + E_ + (c << 3) + 4);
        #pragma unroll
        for (int j = 0; j < 5; j++) {
            const float* kr = &sK[lq0 + t0 + j][c << 3];
            float4 k0v = *reinterpret_cast<const float4*>(kr);
            float4 k1v = *reinterpret_cast<const float4*>(kr + 4);
            d0[j] += qa0.x * k0v.x + qa0.y * k0v.y + qa0.z * k0v.z + qa0.w * k0v.w
                   + qa1.x * k1v.x + qa1.y * k1v.y + qa1.z * k1v.z + qa1.w * k1v.w;
            d1[j] += qb0.x * k0v.x + qb0.y * k0v.y + qb0.z * k0v.z + qb0.w * k0v.w
                   + qb1.x * k1v.x + qb1.y * k1v.y + qb1.z * k1v.z + qb1.w * k1v.w;
        }
    }
    float s0[4], s1[4];
    #pragma unroll
    for (int j = 0; j < 4; j++) {
        s0[j] = d0[j] * SCALING;
        s1[j] = d1[j + 1] * SCALING;
    }

    float mx0 = fmaxf(fmaxf(s0[0], s0[1]), fmaxf(s0[2], s0[3]));
    float mx1 = fmaxf(fmaxf(s1[0], s1[1]), fmaxf(s1[2], s1[3]));
    #pragma unroll
    for (int m = 1; m <= 4; m <<= 1) {
        mx0 = fmaxf(mx0, __shfl_xor_sync(0xffffffffu, mx0, m));
        mx1 = fmaxf(mx1, __shfl_xor_sync(0xffffffffu, mx1, m));
    }
    float sum0 = 0.f, sum1 = 0.f;
    #pragma unroll
    for (int j = 0; j < 4; j++) {
        s0[j] = __expf(s0[j] - mx0); sum0 += s0[j];
        s1[j] = __expf(s1[j] - mx1); sum1 += s1[j];
    }
    #pragma unroll
    for (int m = 1; m <= 4; m <<= 1) {
        sum0 += __shfl_xor_sync(0xffffffffu, sum0, m);
        sum1 += __shfl_xor_sync(0xffffffffu, sum1, m);
    }
    float inv0 = 1.f / sum0, inv1 = 1.f / sum1;
    #pragma unroll
    for (int j = 0; j < 4; j++) {
        sP[lq0][3 + t0 + j]     = s0[j] * inv0;
        sP[lq0 + 1][3 + t0 + j] = s1[j] * inv1;
    }
    __syncthreads();

    // ---- Output phase (quad mapping): quad = tid>>4, 2 dims per thread ----
    const int quad = tid >> 4;        // 0..15
    const int q0   = quad << 2;       // query base
    const int d0c  = (tid & 15) << 1; // dim base (float2)

    float2 o[4];
    #pragma unroll
    for (int qi = 0; qi < 4; qi++) o[qi] = make_float2(0.f, 0.f);

    #pragma unroll
    for (int rr = 0; rr < 35; rr++) {
        float2 v = *reinterpret_cast<const float2*>(&sV[q0 + rr][d0c]);
        #pragma unroll
        for (int qi = 0; qi < 4; qi++) {
            float pr = sP[q0 + qi][3 + rr - qi];  // zero outside valid band
            o[qi].x += pr * v.x;
            o[qi].y += pr * v.y;
        }
    }

    #pragma unroll
    for (int qi = 0; qi < 4; qi++) {
        float* orow = &out[((size_t)(b * N_ + n0 + q0 + qi)) * E_ + be + d0c];
        *reinterpret_cast<float2*>(orow) = o[qi];
    }
}

// ---------------------------------------------------------------------------
// Launch
// ---------------------------------------------------------------------------
extern "C" void kernel_launch(void* const* d_in, const int* in_sizes, int n_in,
                              void* d_out, int out_size) {
    const float* query = (const float*)d_in[0];
    const float* key   = (const float*)d_in[1];
    const float* value = (const float*)d_in[2];
    const float* W     = (const float*)d_in[3];
    const float* bias  = (const float*)d_in[4];
    float* out = (float*)d_out;

    dim3 gProj(E_ / 64, M_ / 128, 3);   // (4, 64, 3)
    proj_kernel<<<gProj, 256>>>(query, key, value, W, bias);

    attn_kernel<<<B_ * H_ * (N_ / 64), 256>>>(bias, out);
}